// round 14
// baseline (speedup 1.0000x reference)
#include <cuda_runtime.h>
#include <cuda_fp16.h>
#include <cstdint>
#include <math.h>

// ---------------------------------------------------------------------------
// SelfAttention via legacy tensor path (mma.sync HMMA, fp16 hi/lo split):
//   GEMM1 (3-term): qkv = hidden @ W          (M=8192,N=3072,K=1024)  B=[K,N]
//   GEMM2 (2-term): scores = Q @ K^T * 1/32   (M=2048,N=2048,K=1024)  B=[N,K]
//   softmax rows (in place)
//   GEMM3 (2-term): out = P @ V               (M=2048,N=1024,K=2048)  B=[K,N]
// 2-term kernels use ks-level fragment double-buffering (LDSM hidden under
// MMAs). R8 (968us) base, BK=32.
// ---------------------------------------------------------------------------

#define BATCH 4
#define SEQ   2048
#define EMB   1024
#define BS    8192

__device__ float g_qkv[(long)BS * 3 * EMB];          // [8192, 3072]
__device__ float g_scores[(long)BATCH * SEQ * SEQ];  // [4, 2048, 2048]

// ---------------- helpers ----------------
__device__ __forceinline__ uint32_t smem_u32(const void* p) {
    uint32_t a;
    asm("{ .reg .u64 t; cvta.to.shared.u64 t, %1; cvt.u32.u64 %0, t; }"
        : "=r"(a) : "l"(p));
    return a;
}

#define LDSM_X4(r, a)                                                        \
    asm volatile("ldmatrix.sync.aligned.m8n8.x4.shared.b16 {%0,%1,%2,%3}, [%4];" \
                 : "=r"((r)[0]), "=r"((r)[1]), "=r"((r)[2]), "=r"((r)[3])    \
                 : "r"(a))

#define LDSM_X4_T(r0, r1, r2, r3, a)                                         \
    asm volatile("ldmatrix.sync.aligned.m8n8.x4.trans.shared.b16 {%0,%1,%2,%3}, [%4];" \
                 : "=r"(r0), "=r"(r1), "=r"(r2), "=r"(r3)                    \
                 : "r"(a))

__device__ __forceinline__ void mma16816(float* c, const uint32_t* a, const uint32_t* b) {
    asm volatile(
        "mma.sync.aligned.m16n8k16.row.col.f32.f16.f16.f32 "
        "{%0,%1,%2,%3}, {%4,%5,%6,%7}, {%8,%9}, {%0,%1,%2,%3};"
        : "+f"(c[0]), "+f"(c[1]), "+f"(c[2]), "+f"(c[3])
        : "r"(a[0]), "r"(a[1]), "r"(a[2]), "r"(a[3]), "r"(b[0]), "r"(b[1]));
}

// split fp32x4 -> hi/lo fp16x4 packed as 2x b32 each
__device__ __forceinline__ void split4(float4 v, uint32_t* h, uint32_t* l) {
    __half h0 = __float2half_rn(v.x), h1 = __float2half_rn(v.y);
    __half h2 = __float2half_rn(v.z), h3 = __float2half_rn(v.w);
    __half l0 = __float2half_rn(v.x - __half2float(h0));
    __half l1 = __float2half_rn(v.y - __half2float(h1));
    __half l2 = __float2half_rn(v.z - __half2float(h2));
    __half l3 = __float2half_rn(v.w - __half2float(h3));
    __half2 ha = __halves2half2(h0, h1), hb = __halves2half2(h2, h3);
    __half2 la = __halves2half2(l0, l1), lb = __halves2half2(l2, l3);
    h[0] = *(uint32_t*)&ha; h[1] = *(uint32_t*)&hb;
    l[0] = *(uint32_t*)&la; l[1] = *(uint32_t*)&lb;
}

__device__ __forceinline__ void hi4(float4 v, uint32_t* h) {
    __half2 ha = __halves2half2(__float2half_rn(v.x), __float2half_rn(v.y));
    __half2 hb = __halves2half2(__float2half_rn(v.z), __float2half_rn(v.w));
    h[0] = *(uint32_t*)&ha; h[1] = *(uint32_t*)&hb;
}

__device__ __forceinline__ void sts64(uint32_t addr, uint32_t a, uint32_t b) {
    asm volatile("st.shared.v2.b32 [%0], {%1,%2};" :: "r"(addr), "r"(a), "r"(b));
}

// ---------------- GEMM ----------------
// Tile: BM=128, BN=128, BK=32 halves. 256 threads = 8 warps (2M x 4N),
// warp tile 64x32 via 4x4 m16n8k16 tiles, 2 K-steps per chunk.
// BNK=0: B gmem [K,N] row-major -> smem [k-row][n] 272B stride, trans-ldmatrix.
// BNK=1: B gmem [N,K] row-major -> smem [n-row][k] 80B stride, ldmatrix.
// NOLOA=1: 2-term split (drop A-lo plane + Alo@Bhi term) + ks frag pipeline.
#define LDA_B   80                   // A smem row stride bytes (32h + 8h pad)
#define LDB_B   272                  // B-trans smem row stride (128h + 8h pad)
#define A_PLANE 10240                // 128 * 80
#define BT_PLANE 8704                // 32 * 272

template <int BNK, int NOLOA>
__global__ __launch_bounds__(256, 1)
void hmma_gemm(const float* __restrict__ A, int lda, long sA,
               const float* __restrict__ B, int ldb, long sB,
               float* __restrict__ C, int ldc, long sC,
               int K, float alpha)
{
    constexpr int ATOT   = (NOLOA ? 1 : 2) * A_PLANE;
    constexpr int BPLANE = BNK ? A_PLANE : BT_PLANE;
    constexpr int STAGE  = ATOT + 2 * BPLANE;

    extern __shared__ char sm[];
    const uint32_t sbase = smem_u32(sm);

    const int tid = threadIdx.x;
    const int lane = tid & 31;
    const int wid = tid >> 5;

    const int bz = blockIdx.z;
    A += (long)bz * sA;
    B += (long)bz * sB;
    C += (long)bz * sC;
    const int row0 = blockIdx.y * 128;
    const int col0 = blockIdx.x * 128;

    const int mb = (wid >> 2) * 64;   // warp M offset
    const int nb = (wid & 3) * 32;    // warp N offset

    // loader per-thread indices
    const int aR = tid >> 3;               // + j*32
    const int aC = (tid & 7) << 2;         // 0..28
    const int bK = tid >> 5;               // + j*8   (BNK=0)
    const int bN = (tid & 31) << 2;        // 0..124  (BNK=0)

    // fragment base addresses (per-lane)
    const uint32_t aFrag = sbase + (uint32_t)((mb + (lane & 15)) * LDA_B + (lane >> 4) * 16);
    const uint32_t bFrag = BNK
        ? sbase + ATOT +
          (uint32_t)((nb + (lane & 7) + ((lane >> 4) & 1) * 8) * LDA_B + ((lane >> 3) & 1) * 16)
        : sbase + ATOT +
          (uint32_t)(((lane & 7) + ((lane >> 3) & 1) * 8) * LDB_B + (nb + (lane >> 4) * 8) * 2);

    float acc[4][4][4];
    #pragma unroll
    for (int i = 0; i < 4; i++)
        #pragma unroll
        for (int j = 0; j < 4; j++)
            #pragma unroll
            for (int e = 0; e < 4; e++) acc[i][j][e] = 0.0f;

    const int nIter = K / 32;
    float4 aReg[4], bReg[4];

    // gmem loads for chunk k0
    auto ldg = [&](int k0) {
        #pragma unroll
        for (int j = 0; j < 4; j++)
            aReg[j] = *reinterpret_cast<const float4*>(
                A + (long)(row0 + j * 32 + aR) * lda + k0 + aC);
        if (BNK) {
            #pragma unroll
            for (int j = 0; j < 4; j++)
                bReg[j] = *reinterpret_cast<const float4*>(
                    B + (long)(col0 + j * 32 + aR) * ldb + k0 + aC);
        } else {
            #pragma unroll
            for (int j = 0; j < 4; j++)
                bReg[j] = *reinterpret_cast<const float4*>(
                    B + (long)(k0 + j * 8 + bK) * ldb + col0 + bN);
        }
    };
    // convert + store staged regs into stage st
    auto sts = [&](uint32_t st) {
        #pragma unroll
        for (int j = 0; j < 4; j++) {
            uint32_t ad = sbase + st + (uint32_t)((j * 32 + aR) * LDA_B + aC * 2);
            if (NOLOA) {
                uint32_t h[2];
                hi4(aReg[j], h);
                sts64(ad, h[0], h[1]);
            } else {
                uint32_t h[2], l[2];
                split4(aReg[j], h, l);
                sts64(ad, h[0], h[1]);
                sts64(ad + A_PLANE, l[0], l[1]);
            }
        }
        #pragma unroll
        for (int j = 0; j < 4; j++) {
            uint32_t h[2], l[2];
            split4(bReg[j], h, l);
            uint32_t ad;
            if (BNK)
                ad = sbase + st + ATOT + (uint32_t)((j * 32 + aR) * LDA_B + aC * 2);
            else
                ad = sbase + st + ATOT + (uint32_t)((j * 8 + bK) * LDB_B + bN * 2);
            sts64(ad, h[0], h[1]);
            sts64(ad + BPLANE, l[0], l[1]);
        }
    };

    // fragment buffers (double for NOLOA pipeline; al unused when NOLOA)
    uint32_t ah[2][4][4], al[2][4][4], bh[2][4][2], bl[2][4][2];

    auto ldfrag = [&](int bf, uint32_t st, int ks) {
        #pragma unroll
        for (int i = 0; i < 4; i++) {
            uint32_t ad = aFrag + st + (uint32_t)(i * 16 * LDA_B + ks * 32);
            LDSM_X4(ah[bf][i], ad);
            if (!NOLOA) LDSM_X4(al[bf][i], ad + A_PLANE);
        }
        #pragma unroll
        for (int j2 = 0; j2 < 2; j2++) {
            if (BNK) {
                uint32_t bd = bFrag + st + (uint32_t)(j2 * 16 * LDA_B + ks * 32);
                LDSM_X4(bh[bf][2 * j2], bd);
                LDSM_X4(bl[bf][2 * j2], bd + BPLANE);
            } else {
                uint32_t bd = bFrag + st + (uint32_t)(ks * 16 * LDB_B + j2 * 32);
                LDSM_X4_T(bh[bf][2 * j2][0], bh[bf][2 * j2][1],
                          bh[bf][2 * j2 + 1][0], bh[bf][2 * j2 + 1][1], bd);
                LDSM_X4_T(bl[bf][2 * j2][0], bl[bf][2 * j2][1],
                          bl[bf][2 * j2 + 1][0], bl[bf][2 * j2 + 1][1], bd + BPLANE);
            }
        }
    };

    auto domma = [&](int bf) {
        #pragma unroll
        for (int i = 0; i < 4; i++)
            #pragma unroll
            for (int j = 0; j < 4; j++) mma16816(acc[i][j], ah[bf][i], bh[bf][j]);
        #pragma unroll
        for (int i = 0; i < 4; i++)
            #pragma unroll
            for (int j = 0; j < 4; j++) mma16816(acc[i][j], ah[bf][i], bl[bf][j]);
        if (!NOLOA) {
            #pragma unroll
            for (int i = 0; i < 4; i++)
                #pragma unroll
                for (int j = 0; j < 4; j++) mma16816(acc[i][j], al[bf][i], bh[bf][j]);
        }
    };

    ldg(0);
    sts(0);
    __syncthreads();
    if (NOLOA) ldfrag(0, 0, 0);

    for (int kb = 0; kb < nIter; kb++) {
        const uint32_t st = (uint32_t)(kb & 1) * STAGE;
        const uint32_t stN = (uint32_t)((kb + 1) & 1) * STAGE;
        if (kb + 1 < nIter) ldg((kb + 1) * 32);

        if (NOLOA) {
            // ks pipeline: prefetch ks1 frags, compute ks0; sts overlaps ks1.
            ldfrag(1, st, 1);
            domma(0);
            if (kb + 1 < nIter) sts(stN);
            domma(1);
            __syncthreads();
            if (kb + 1 < nIter) ldfrag(0, stN, 0);
        } else {
            #pragma unroll
            for (int ks = 0; ks < 2; ks++) {
                ldfrag(0, st, ks);
                domma(0);
            }
            if (kb + 1 < nIter) sts(stN);
            __syncthreads();
        }
    }

    // epilogue
    #pragma unroll
    for (int i = 0; i < 4; i++) {
        const int r = row0 + mb + i * 16 + (lane >> 2);
        #pragma unroll
        for (int j = 0; j < 4; j++) {
            const int c = col0 + nb + j * 8 + (lane & 3) * 2;
            float2 v0 = make_float2(acc[i][j][0] * alpha, acc[i][j][1] * alpha);
            float2 v1 = make_float2(acc[i][j][2] * alpha, acc[i][j][3] * alpha);
            *reinterpret_cast<float2*>(C + (long)r * ldc + c) = v0;
            *reinterpret_cast<float2*>(C + (long)(r + 8) * ldc + c) = v1;
        }
    }
}

// ---------------- softmax: one row (2048) per 256-thread block ----------------
__global__ __launch_bounds__(256)
void softmax_kernel(float* __restrict__ scores)
{
    __shared__ float red[8];
    const long row = blockIdx.x;
    float4* r4 = reinterpret_cast<float4*>(scores + row * (long)SEQ);
    const int tid = threadIdx.x;
    const int wid = tid >> 5, lane = tid & 31;

    float4 a = r4[tid];
    float4 b = r4[tid + 256];

    float m = fmaxf(fmaxf(fmaxf(a.x, a.y), fmaxf(a.z, a.w)),
                    fmaxf(fmaxf(b.x, b.y), fmaxf(b.z, b.w)));
    #pragma unroll
    for (int o = 16; o; o >>= 1) m = fmaxf(m, __shfl_xor_sync(0xffffffffu, m, o));
    if (lane == 0) red[wid] = m;
    __syncthreads();
    float rowmax = red[0];
    #pragma unroll
    for (int i = 1; i < 8; i++) rowmax = fmaxf(rowmax, red[i]);
    __syncthreads();

    a.x = __expf(a.x - rowmax); a.y = __expf(a.y - rowmax);
    a.z = __expf(a.z - rowmax); a.w = __expf(a.w - rowmax);
    b.x = __expf(b.x - rowmax); b.y = __expf(b.y - rowmax);
    b.z = __expf(b.z - rowmax); b.w = __expf(b.w - rowmax);

    float s = a.x + a.y + a.z + a.w + b.x + b.y + b.z + b.w;
    #pragma unroll
    for (int o = 16; o; o >>= 1) s += __shfl_xor_sync(0xffffffffu, s, o);
    if (lane == 0) red[wid] = s;
    __syncthreads();
    float tot = red[0];
    #pragma unroll
    for (int i = 1; i < 8; i++) tot += red[i];
    const float inv = 1.0f / tot;

    a.x *= inv; a.y *= inv; a.z *= inv; a.w *= inv;
    b.x *= inv; b.y *= inv; b.z *= inv; b.w *= inv;
    r4[tid] = a;
    r4[tid + 256] = b;
}

// ---------------- launch ----------------
extern "C" void kernel_launch(void* const* d_in, const int* in_sizes, int n_in,
                              void* d_out, int out_size)
{
    const float* hidden = (const float*)d_in[0];   // [4,2048,1024]
    const float* W      = (const float*)d_in[1];   // [1024,3072]
    float* out          = (float*)d_out;           // [4,2048,1024]

    float* qkv = nullptr; float* scores = nullptr;
    cudaGetSymbolAddress((void**)&qkv, g_qkv);
    cudaGetSymbolAddress((void**)&scores, g_scores);

    constexpr int SM1 = 2 * (2 * A_PLANE + 2 * BT_PLANE);  // 75776  G1 (3-term)
    constexpr int SM2 = 2 * (1 * A_PLANE + 2 * A_PLANE);   // 61440  G2 (2-term, BNK=1)
    constexpr int SM3 = 2 * (1 * A_PLANE + 2 * BT_PLANE);  // 55296  G3 (2-term)
    cudaFuncSetAttribute(hmma_gemm<0, 0>, cudaFuncAttributeMaxDynamicSharedMemorySize, SM1);
    cudaFuncSetAttribute(hmma_gemm<1, 1>, cudaFuncAttributeMaxDynamicSharedMemorySize, SM2);
    cudaFuncSetAttribute(hmma_gemm<0, 1>, cudaFuncAttributeMaxDynamicSharedMemorySize, SM3);

    // 1) qkv = hidden @ W   (M=8192, N=3072, K=1024), B=[K,N], 3-term
    hmma_gemm<0, 0><<<dim3(3 * EMB / 128, BS / 128, 1), 256, SM1>>>(
        hidden, EMB, 0,
        W, 3 * EMB, 0,
        qkv, 3 * EMB, 0,
        EMB, 1.0f);

    // 2) scores[b] = Q[b] @ K[b]^T * 1/32   (B=[N,K]), 2-term + pipeline
    hmma_gemm<1, 1><<<dim3(SEQ / 128, SEQ / 128, BATCH), 256, SM2>>>(
        qkv, 3 * EMB, (long)SEQ * 3 * EMB,
        qkv + EMB, 3 * EMB, (long)SEQ * 3 * EMB,
        scores, SEQ, (long)SEQ * SEQ,
        EMB, 1.0f / 32.0f);

    // 3) softmax rows (in place)
    softmax_kernel<<<BATCH * SEQ, 256>>>(scores);

    // 4) out[b] = P[b] @ V[b]   (B=[K,N]), 2-term + pipeline
    hmma_gemm<0, 1><<<dim3(EMB / 128, SEQ / 128, BATCH), 256, SM3>>>(
        scores, SEQ, (long)SEQ * SEQ,
        qkv + 2 * EMB, 3 * EMB, (long)SEQ * 3 * EMB,
        out, EMB, (long)SEQ * EMB,
        SEQ, 1.0f);
}